// round 15
// baseline (speedup 1.0000x reference)
#include <cuda_runtime.h>
#include <cuda_fp16.h>
#include <mma.h>
#include <cstdint>
#include <cstddef>

using namespace nvcuda;

#define H_DIM 128
#define MAX_E 1048576
#define MAX_NODES 100480
#define MAX_SIDE 51200
#define PSH 16                         // fp16 p-table stride (halfs)
#define MAX_C 12
#define SCAN_B 256
#define MAX_SCAN_BLK 512
#define WLD 136                        // padded ld for 128-wide fp16 weight tile
#define LDKU 40                        // padded ld, K=32
#define LDKM 72                        // padded ld, K=64
#define ST_LD 20                       // per-warp stage ld (floats)
#define ST_WARP (16 * ST_LD)           // 320 floats = 1280 B per warp
#define TG 512                         // threads per GEMM block (16 warps)
#define SMEM_F64  (2 * 128 * LDKM * 2)         // fused1 <32,64>: 36864
#define SMEM_F128 (2 * 128 * (128 + 8) * 2)    // fallback <128,128>: 69632
#define SMEM_LIN  (128 * WLD * 2)              // layer GEMM: 34816

// ---------------- device scratch (no allocations allowed) ----------------
__device__ __align__(16) __half g_xh [(size_t)MAX_NODES * H_DIM];  // fp16 x
__device__ __align__(16) __half g_hsh[(size_t)MAX_NODES * H_DIM];  // fp16 hs
__device__ int   g_deg   [MAX_NODES];        // all-zero at entry; restored in scan3
__device__ int   g_off   [MAX_NODES + 1];
__device__ int   g_cursor[MAX_NODES];
__device__ float g_dinv  [MAX_NODES];
__device__ int   g_row[MAX_E];
__device__ int   g_col[MAX_E];
__device__ int   g_csr[MAX_E];            // source node per bucketed edge
__device__ int   g_bsum [MAX_SCAN_BLK];
__device__ __align__(16) __half g_puh[(size_t)MAX_SIDE * PSH];
__device__ __align__(16) __half g_pmh[(size_t)MAX_SIDE * PSH];
// combined layer-1 weights (fp16, padded layouts) + biases (fp32)
__device__ __align__(16) __half g_W1uh[128 * LDKU];
__device__ __align__(16) __half g_W1mh[128 * LDKM];
__device__ __align__(16) __half g_W2h [128 * WLD];
__device__ float g_b1u[128];
__device__ float g_b1m[128];

__device__ __forceinline__ uint2 f4_to_h4(float4 v)
{
    __half2 h0 = __floats2half2_rn(v.x, v.y);
    __half2 h1 = __floats2half2_rn(v.z, v.w);
    uint2 u;
    u.x = *reinterpret_cast<uint32_t*>(&h0);
    u.y = *reinterpret_cast<uint32_t*>(&h1);
    return u;
}

// ---------------- convert edges + degree count; spare blocks prep weights ------
__global__ void mp_convert_kernel(const void* ei, int E, int EB,
                                  const float* __restrict__ Wu,
                                  const float* __restrict__ bu,
                                  const float* __restrict__ Wm,
                                  const float* __restrict__ bm,
                                  const float* __restrict__ W1,
                                  const float* __restrict__ b1,
                                  const float* __restrict__ W2,
                                  int Fu, int Fm)
{
    if ((int)blockIdx.x < EB) {
        const long long* p64 = (const long long*)ei;
        long long probe = p64[threadIdx.x & 31];
        unsigned ok = __ballot_sync(0xffffffffu,
                                    probe >= 0 && probe < (1LL << 32));
        bool is64 = (ok == 0xffffffffu);

        int e = blockIdx.x * blockDim.x + threadIdx.x;
        if (e >= E) return;
        int r, c;
        if (is64) {
            r = (int)p64[e];
            c = (int)p64[(size_t)E + e];
        } else {
            const int* p = (const int*)ei;
            r = p[e];
            c = p[E + e];
        }
        g_row[e] = r;
        g_col[e] = c;
        atomicAdd(&g_deg[c], 1);
    } else {
        int idx = ((int)blockIdx.x - EB) * blockDim.x + threadIdx.x;
        int totU = 128 * Fu, totM = 128 * Fm;
        if (idx < totU) {
            int o = idx / Fu, f = idx - o * Fu;
            float s = 0.f;
            for (int j = 0; j < 128; j++) s += W1[o * 128 + j] * Wu[j * Fu + f];
            g_W1uh[o * LDKU + f] = __float2half_rn(s);
        } else if (idx < totU + totM) {
            int k = idx - totU;
            int o = k / Fm, f = k - o * Fm;
            float s = 0.f;
            for (int j = 0; j < 128; j++) s += W1[o * 128 + j] * Wm[j * Fm + f];
            g_W1mh[o * LDKM + f] = __float2half_rn(s);
        } else if (idx < totU + totM + 256) {
            int k = idx - totU - totM;
            int o = k & 127;
            bool isM = k >= 128;
            const float* bb = isM ? bm : bu;
            float s = b1[o];
            for (int j = 0; j < 128; j++) s += W1[o * 128 + j] * bb[j];
            if (isM) g_b1m[o] = s; else g_b1u[o] = s;
        } else if (idx < totU + totM + 256 + 128 * 128) {
            int k = idx - totU - totM - 256;
            int o = k >> 7, f = k & 127;
            g_W2h[o * WLD + f] = __float2half_rn(W2[o * 128 + f]);
        }
    }
}

// ---------------- scan phase 1: per-block exclusive scan + block sums ----------
__global__ void mp_scan1_kernel(int N)
{
    __shared__ int sh[SCAN_B];
    int t = threadIdx.x;
    int i = blockIdx.x * SCAN_B + t;
    int v = (i < N) ? g_deg[i] : 0;
    sh[t] = v;
    __syncthreads();
    #pragma unroll
    for (int ofs = 1; ofs < SCAN_B; ofs <<= 1) {
        int u = (t >= ofs) ? sh[t - ofs] : 0;
        __syncthreads();
        sh[t] += u;
        __syncthreads();
    }
    if (i < N) g_off[i] = sh[t] - v;
    if (t == SCAN_B - 1) g_bsum[blockIdx.x] = sh[t];
}

// ---------------- scan phase 2: block prefix + cursor/dinv init + deg restore --
__global__ void mp_scan3_kernel(int N)
{
    __shared__ int s_prefix;
    int t = threadIdx.x;
    if (t < 32) {
        int b = blockIdx.x;
        int sum = 0;
        for (int k = t; k < b; k += 32) sum += g_bsum[k];
        #pragma unroll
        for (int ofs = 16; ofs > 0; ofs >>= 1)
            sum += __shfl_down_sync(0xffffffffu, sum, ofs);
        if (t == 0) s_prefix = sum;
    }
    __syncthreads();
    int i = blockIdx.x * blockDim.x + t;
    if (i >= N) return;
    int d   = g_deg[i];
    int off = g_off[i] + s_prefix;
    g_off[i]    = off;
    g_cursor[i] = off;
    g_dinv[i]   = rsqrtf((float)(d + 1));
    g_deg[i]    = 0;                        // restore invariant
    if (i == N - 1) g_off[N] = off + d;
}

// ---------------- bucket fill: csr[pos] = row (standalone, fallback path) ------
__global__ void mp_fill_kernel(int E)
{
    int e = blockIdx.x * blockDim.x + threadIdx.x;
    if (e >= E) return;
    int pos = atomicAdd(&g_cursor[g_col[e]], 1);
    g_csr[pos] = g_row[e];
}

// ---------------- per-warp fragment epilogue: bias + optional scale -> fp16 ----
template<bool SCALE>
__device__ __forceinline__ void mp_epilogue_frag(
    float* st, wmma::fragment<wmma::accumulator, 16, 16, 16, float>& acc,
    int col0, int wrow0, int N, const float* __restrict__ B,
    const float* __restrict__ dinv_base, __half* __restrict__ Y, int lane)
{
    wmma::store_matrix_sync(st, acc, ST_LD, wmma::mem_row_major);
    __syncwarp();
    int r = lane >> 1;
    int h = lane & 1;
    int node = wrow0 + r;
    int c8 = col0 + h * 8;
    if (node < N) {
        float s = SCALE ? dinv_base[node] : 1.f;
        const float* sp = st + r * ST_LD + h * 8;
        float4 v0 = *reinterpret_cast<const float4*>(sp);
        float4 v1 = *reinterpret_cast<const float4*>(sp + 4);
        __half2 hh[4];
        hh[0] = __floats2half2_rn((v0.x + B[c8 + 0]) * s, (v0.y + B[c8 + 1]) * s);
        hh[1] = __floats2half2_rn((v0.z + B[c8 + 2]) * s, (v0.w + B[c8 + 3]) * s);
        hh[2] = __floats2half2_rn((v1.x + B[c8 + 4]) * s, (v1.y + B[c8 + 5]) * s);
        hh[3] = __floats2half2_rn((v1.z + B[c8 + 6]) * s, (v1.w + B[c8 + 7]) * s);
        *reinterpret_cast<uint4*>(Y + (size_t)node * H_DIM + c8) =
            *reinterpret_cast<const uint4*>(hh);
    }
    __syncwarp();
}

// ---------------- wmma node linear, pre-converted fp16 weights (padded LDK) ----
template<int K>
__device__ __forceinline__ void mp_wmma_xf16_body(
    const float* __restrict__ X, int N,
    const __half* __restrict__ Wg,       // [128][K+8] fp16, pre-padded
    const float* __restrict__ B,
    const float* __restrict__ dinv_base,
    __half* __restrict__ Y, int bid)
{
    constexpr int LDK = K + 8;
    extern __shared__ __align__(16) char smem_raw[];
    __half* Xh    = reinterpret_cast<__half*>(smem_raw);   // 128 x LDK
    __half* Wh    = Xh + 128 * LDK;                        // 128 x LDK
    float*  stage = reinterpret_cast<float*>(smem_raw);    // overlays after loop

    const int tid  = threadIdx.x;
    const int w    = tid >> 5;
    const int lane = tid & 31;
    const int wr   = w >> 1;
    const int wc   = w & 1;
    const int tile0 = bid * 128;
    const int wrow0 = tile0 + wr * 16;

    constexpr int KV = K / 4;
    for (int i = tid; i < 128 * KV; i += TG) {
        int n = i / KV, q = i - n * KV;
        int node = tile0 + n;
        if (node >= N) node = N - 1;                       // stores guarded
        float4 v = *reinterpret_cast<const float4*>(X + (size_t)node * K + q * 4);
        *reinterpret_cast<uint2*>(Xh + n * LDK + q * 4) = f4_to_h4(v);
    }
    for (int i = tid; i < 128 * LDK / 8; i += TG)
        reinterpret_cast<uint4*>(Wh)[i] =
            reinterpret_cast<const uint4*>(Wg)[i];
    __syncthreads();

    wmma::fragment<wmma::accumulator, 16, 16, 16, float> acc[4];
    #pragma unroll
    for (int n = 0; n < 4; n++) wmma::fill_fragment(acc[n], 0.f);

    #pragma unroll
    for (int k0 = 0; k0 < K / 16; k0++) {
        wmma::fragment<wmma::matrix_a, 16, 16, 16, __half, wmma::row_major> a;
        wmma::load_matrix_sync(a, Xh + wr * 16 * LDK + k0 * 16, LDK);
        #pragma unroll
        for (int n = 0; n < 4; n++) {
            wmma::fragment<wmma::matrix_b, 16, 16, 16, __half, wmma::col_major> b;
            wmma::load_matrix_sync(b, Wh + (wc * 64 + n * 16) * LDK + k0 * 16, LDK);
            wmma::mma_sync(acc[n], a, b, acc[n]);
        }
    }
    __syncthreads();   // tiles dead; per-warp stage overlays them

    float* st = stage + w * ST_WARP;
    #pragma unroll
    for (int n = 0; n < 4; n++)
        mp_epilogue_frag<true>(st, acc[n], wc * 64 + n * 16, wrow0, N,
                               B, dinv_base, Y, lane);
}

// Fused layer-1 (+ absorbed bucket fill in tail blocks).
template<int KU, int KM>
__global__ void __launch_bounds__(TG)
mp_fused1_kernel(const float* __restrict__ Xu, int Nu,
                 const float* __restrict__ Xm, int Nm,
                 __half* __restrict__ Y, int gU, int gM, int E)
{
    int b = (int)blockIdx.x;
    if (b < gU) {
        mp_wmma_xf16_body<KU>(Xu, Nu, g_W1uh, g_b1u, g_dinv, Y, b);
    } else if (b < gU + gM) {
        mp_wmma_xf16_body<KM>(Xm, Nm, g_W1mh, g_b1m, g_dinv + Nu,
                              Y + (size_t)Nu * H_DIM, b - gU);
    } else {
        int e = (b - gU - gM) * TG + threadIdx.x;
        if (e < E) {
            int pos = atomicAdd(&g_cursor[g_col[e]], 1);
            g_csr[pos] = g_row[e];
        }
    }
}

// ---------------- fallback fp32-weight body (odd K shapes) ---------------------
template<int K, bool SCALE>
__device__ __forceinline__ void mp_wmma_xf_body(
    const float* __restrict__ X, int N,
    const float* __restrict__ W,
    const float* __restrict__ B,
    const float* __restrict__ dinv_base,
    __half* __restrict__ Y, int bid)
{
    constexpr int LDK = K + 8;
    extern __shared__ __align__(16) char smem_raw[];
    __half* Xh    = reinterpret_cast<__half*>(smem_raw);
    __half* Wh    = Xh + 128 * LDK;
    float*  stage = reinterpret_cast<float*>(smem_raw);

    const int tid  = threadIdx.x;
    const int w    = tid >> 5;
    const int lane = tid & 31;
    const int wr   = w >> 1;
    const int wc   = w & 1;
    const int tile0 = bid * 128;
    const int wrow0 = tile0 + wr * 16;

    constexpr int KV = K / 4;
    for (int i = tid; i < 128 * KV; i += TG) {
        int n = i / KV, q = i - n * KV;
        int node = tile0 + n;
        if (node >= N) node = N - 1;
        float4 v = *reinterpret_cast<const float4*>(X + (size_t)node * K + q * 4);
        *reinterpret_cast<uint2*>(Xh + n * LDK + q * 4) = f4_to_h4(v);
    }
    for (int i = tid; i < 128 * KV; i += TG) {
        int n = i / KV, q = i - n * KV;
        float4 v = *reinterpret_cast<const float4*>(W + (size_t)n * K + q * 4);
        *reinterpret_cast<uint2*>(Wh + n * LDK + q * 4) = f4_to_h4(v);
    }
    __syncthreads();

    wmma::fragment<wmma::accumulator, 16, 16, 16, float> acc[4];
    #pragma unroll
    for (int n = 0; n < 4; n++) wmma::fill_fragment(acc[n], 0.f);

    #pragma unroll
    for (int k0 = 0; k0 < K / 16; k0++) {
        wmma::fragment<wmma::matrix_a, 16, 16, 16, __half, wmma::row_major> a;
        wmma::load_matrix_sync(a, Xh + wr * 16 * LDK + k0 * 16, LDK);
        #pragma unroll
        for (int n = 0; n < 4; n++) {
            wmma::fragment<wmma::matrix_b, 16, 16, 16, __half, wmma::col_major> b;
            wmma::load_matrix_sync(b, Wh + (wc * 64 + n * 16) * LDK + k0 * 16, LDK);
            wmma::mma_sync(acc[n], a, b, acc[n]);
        }
    }
    __syncthreads();

    float* st = stage + w * ST_WARP;
    #pragma unroll
    for (int n = 0; n < 4; n++)
        mp_epilogue_frag<SCALE>(st, acc[n], wc * 64 + n * 16, wrow0, N,
                                B, dinv_base, Y, lane);
}

template<int KU, int KM>
__global__ void __launch_bounds__(TG)
mp_transform_kernel(const float* __restrict__ Xu, int Nu,
                    const float* __restrict__ Wu,
                    const float* __restrict__ Bu,
                    const float* __restrict__ Xm, int Nm,
                    const float* __restrict__ Wm,
                    const float* __restrict__ Bm,
                    __half* __restrict__ Y, int gU)
{
    if ((int)blockIdx.x < gU)
        mp_wmma_xf_body<KU, false>(Xu, Nu, Wu, Bu, nullptr, Y, blockIdx.x);
    else
        mp_wmma_xf_body<KM, false>(Xm, Nm, Wm, Bm, nullptr,
                                   Y + (size_t)Nu * H_DIM, blockIdx.x - gU);
}

// ---------------- layer GEMM, pre-converted fp16 W2 (padded WLD) ---------------
__global__ void __launch_bounds__(TG)
mp_wmma_linear_h_kernel(const __half* __restrict__ A, int N,
                        const float* __restrict__ B,
                        __half* __restrict__ Y)
{
    extern __shared__ __align__(16) char smem_raw[];
    __half* Wh    = reinterpret_cast<__half*>(smem_raw);   // 128 x WLD
    float*  stage = reinterpret_cast<float*>(smem_raw);    // overlays Wh

    const int tid  = threadIdx.x;
    const int w    = tid >> 5;
    const int lane = tid & 31;
    const int wr   = w >> 1;
    const int wc   = w & 1;
    const int wrow0 = blockIdx.x * 128 + wr * 16;

    for (int i = tid; i < 128 * WLD / 8; i += TG)
        reinterpret_cast<uint4*>(Wh)[i] =
            reinterpret_cast<const uint4*>(g_W2h)[i];
    __syncthreads();

    wmma::fragment<wmma::accumulator, 16, 16, 16, float> acc[4];
    #pragma unroll
    for (int n = 0; n < 4; n++) wmma::fill_fragment(acc[n], 0.f);

    int arow = wrow0;
    if (arow + 16 > N) arow = (N > 16) ? N - 16 : 0;

    #pragma unroll
    for (int k0 = 0; k0 < 8; k0++) {
        wmma::fragment<wmma::matrix_a, 16, 16, 16, __half, wmma::row_major> a;
        wmma::load_matrix_sync(a, A + (size_t)arow * H_DIM + k0 * 16, H_DIM);
        #pragma unroll
        for (int n = 0; n < 4; n++) {
            wmma::fragment<wmma::matrix_b, 16, 16, 16, __half, wmma::col_major> b;
            wmma::load_matrix_sync(b, Wh + (wc * 64 + n * 16) * WLD + k0 * 16, WLD);
            wmma::mma_sync(acc[n], a, b, acc[n]);
        }
    }
    __syncthreads();

    float* st = stage + w * ST_WARP;
    #pragma unroll
    for (int n = 0; n < 4; n++)
        mp_epilogue_frag<true>(st, acc[n], wc * 64 + n * 16, arow, N,
                               B, g_dinv, Y, lane);
}

// Fallback layer GEMM with fp32 W conversion in-kernel.
__global__ void __launch_bounds__(TG)
mp_wmma_linear_kernel(const __half* __restrict__ A, int N,
                      const float* __restrict__ W,
                      const float* __restrict__ B,
                      __half* __restrict__ Y)
{
    extern __shared__ __align__(16) char smem_raw[];
    __half* Wh    = reinterpret_cast<__half*>(smem_raw);
    float*  stage = reinterpret_cast<float*>(smem_raw);

    const int tid  = threadIdx.x;
    const int w    = tid >> 5;
    const int lane = tid & 31;
    const int wr   = w >> 1;
    const int wc   = w & 1;
    const int wrow0 = blockIdx.x * 128 + wr * 16;

    for (int i = tid; i < 128 * 64; i += TG) {
        int o = i >> 6, q = i & 63;
        float2 v = reinterpret_cast<const float2*>(W + (size_t)o * 128)[q];
        reinterpret_cast<__half2*>(Wh + o * WLD)[q] = __floats2half2_rn(v.x, v.y);
    }
    __syncthreads();

    wmma::fragment<wmma::accumulator, 16, 16, 16, float> acc[4];
    #pragma unroll
    for (int n = 0; n < 4; n++) wmma::fill_fragment(acc[n], 0.f);

    int arow = wrow0;
    if (arow + 16 > N) arow = (N > 16) ? N - 16 : 0;

    #pragma unroll
    for (int k0 = 0; k0 < 8; k0++) {
        wmma::fragment<wmma::matrix_a, 16, 16, 16, __half, wmma::row_major> a;
        wmma::load_matrix_sync(a, A + (size_t)arow * H_DIM + k0 * 16, H_DIM);
        #pragma unroll
        for (int n = 0; n < 4; n++) {
            wmma::fragment<wmma::matrix_b, 16, 16, 16, __half, wmma::col_major> b;
            wmma::load_matrix_sync(b, Wh + (wc * 64 + n * 16) * WLD + k0 * 16, WLD);
            wmma::mma_sync(acc[n], a, b, acc[n]);
        }
    }
    __syncthreads();

    float* st = stage + w * ST_WARP;
    #pragma unroll
    for (int n = 0; n < 4; n++)
        mp_epilogue_frag<true>(st, acc[n], wc * 64 + n * 16, arow, N,
                               B, g_dinv, Y, lane);
}

// ---------------- aggregate core: a[8] = relu(dinv*(hs[n] + sum hs[src])) ------
__device__ __forceinline__ void mp_acc_add8(float* a, uint4 v)
{
    const __half2* hv = reinterpret_cast<const __half2*>(&v);
    #pragma unroll
    for (int k = 0; k < 4; k++) {
        float2 f = __half22float2(hv[k]);
        a[2 * k]     += f.x;
        a[2 * k + 1] += f.y;
    }
}

// PROJ=false: write xh.  PROJ=true: project to C dims -> fp16 p tables
// (per-lane dims are consecutive: lane hl holds dims [hl*8, hl*8+8)).
template<bool PROJ>
__global__ void mp_aggregate_kernel(int N, int Nu,
                                    const float* __restrict__ We,
                                    const float* __restrict__ be, int C)
{
    int id = blockIdx.x * blockDim.x + threadIdx.x;
    int n = id >> 5;
    if (n >= N) return;
    int lane = id & 31;
    int half = lane >> 4;
    int hl   = lane & 15;

    const uint4* hsp = reinterpret_cast<const uint4*>(g_hsh);   // row = 16 uint4

    float a[8];
    #pragma unroll
    for (int c = 0; c < 8; c++) a[c] = 0.f;

    if (half == 0)                                              // self-loop
        mp_acc_add8(a, __ldg(hsp + (size_t)n * 16 + hl));

    int beg = g_off[n];
    int end = g_off[n + 1];
    for (int base = beg; base < end; base += 32) {
        int m = end - base;
        if (m > 32) m = 32;
        int idx = (lane < m) ? g_csr[base + lane] : 0;
        int j = 0;
        for (; j + 2 <= m; j += 2) {
            int r = __shfl_sync(0xffffffffu, idx, j + half);
            mp_acc_add8(a, __ldg(hsp + (size_t)r * 16 + hl));
        }
        if (j < m) {                                            // odd tail
            int r = __shfl_sync(0xffffffffu, idx, j);
            if (half == 0)
                mp_acc_add8(a, __ldg(hsp + (size_t)r * 16 + hl));
        }
    }

    #pragma unroll
    for (int c = 0; c < 8; c++)
        a[c] += __shfl_xor_sync(0xffffffffu, a[c], 16);

    float s = g_dinv[n];
    #pragma unroll
    for (int c = 0; c < 8; c++) a[c] = fmaxf(a[c] * s, 0.f);

    if (!PROJ) {
        if (half == 0) {
            __half2 h[4];
            #pragma unroll
            for (int j = 0; j < 4; j++)
                h[j] = __floats2half2_rn(a[2 * j], a[2 * j + 1]);
            reinterpret_cast<uint4*>(g_xh)[(size_t)n * 16 + hl] =
                *reinterpret_cast<const uint4*>(h);
        }
    } else {
        // project: p[c] = sum_d x[d] * We[c][wo+d]; lane owns dims hl*8..+8
        bool isU = n < Nu;
        int wo = (isU ? 0 : H_DIM) + hl * 8;
        float p[MAX_C];
        for (int c = 0; c < C; c++) {
            const float* wrow = We + (size_t)c * (2 * H_DIM) + wo;
            float4 w0 = *reinterpret_cast<const float4*>(wrow);
            float4 w1 = *reinterpret_cast<const float4*>(wrow + 4);
            p[c] = a[0] * w0.x + a[1] * w0.y + a[2] * w0.z + a[3] * w0.w
                 + a[4] * w1.x + a[5] * w1.y + a[6] * w1.z + a[7] * w1.w;
        }
        #pragma unroll
        for (int ofs = 1; ofs <= 8; ofs <<= 1)
            for (int c = 0; c < C; c++)
                p[c] += __shfl_xor_sync(0xffffffffu, p[c], ofs);
        if (lane == 0) {
            __half* dst = isU ? (g_puh + (size_t)n * PSH)
                              : (g_pmh + (size_t)(n - Nu) * PSH);
            for (int c = 0; c < C; c++)
                dst[c] = __float2half_rn(p[c] + (isU ? be[c] : 0.f));
        }
    }
}

// ---------------- standalone projection (fallback path) ------------------------
__global__ void mp_proj_kernel(const float* __restrict__ We,
                               const float* __restrict__ be,
                               int Nu, int Nm, int C)
{
    __shared__ float WeS[MAX_C][2 * H_DIM];
    __shared__ float beS[MAX_C];
    int tid = threadIdx.x;
    for (int i = tid; i < C * 2 * H_DIM; i += blockDim.x)
        WeS[i / (2 * H_DIM)][i % (2 * H_DIM)] = We[i];
    if (tid < C) beS[tid] = be[tid];
    __syncthreads();

    int n = blockIdx.x * blockDim.x + tid;
    if (n >= Nu + Nm) return;
    bool isU = n < Nu;
    const uint2* src = reinterpret_cast<const uint2*>(g_xh + (size_t)n * H_DIM);
    int wo = isU ? 0 : H_DIM;

    float acc[MAX_C];
    #pragma unroll
    for (int c = 0; c < MAX_C; c++) acc[c] = (c < C && isU) ? beS[c] : 0.f;

    #pragma unroll 4
    for (int q = 0; q < H_DIM / 4; q++) {
        uint2 u = src[q];
        __half2 ah = *reinterpret_cast<__half2*>(&u.x);
        __half2 bh = *reinterpret_cast<__half2*>(&u.y);
        float2 fa = __half22float2(ah);
        float2 fb = __half22float2(bh);
        int k = q * 4 + wo;
        #pragma unroll
        for (int c = 0; c < MAX_C; c++) {
            if (c < C) {
                acc[c] += fa.x * WeS[c][k + 0] + fa.y * WeS[c][k + 1]
                        + fb.x * WeS[c][k + 2] + fb.y * WeS[c][k + 3];
            }
        }
    }

    __half* dst = isU ? (g_puh + (size_t)n * PSH)
                      : (g_pmh + (size_t)(n - Nu) * PSH);
    for (int c = 0; c < C; c++) dst[c] = __float2half_rn(acc[c]);
}

// ---------------- out[e] = pu[row[e]] + pm[col[e]]  (fp16 tables, fp32 out) -----
__global__ void mp_edge_out_kernel(float* __restrict__ out, int E, int C)
{
    int e = blockIdx.x * blockDim.x + threadIdx.x;
    if (e >= E) return;
    int r = g_row[e];
    int c = g_col[e];
    const __half* a = g_puh + (size_t)r * PSH;
    const __half* b = g_pmh + (size_t)c * PSH;
    float* o = out + (size_t)e * C;
    if (C == 10) {
        uint4 ua = *reinterpret_cast<const uint4*>(a);
        uint4 ub = *reinterpret_cast<const uint4*>(b);
        uint32_t ua2 = *reinterpret_cast<const uint32_t*>(a + 8);
        uint32_t ub2 = *reinterpret_cast<const uint32_t*>(b + 8);
        const __half2* ha = reinterpret_cast<const __half2*>(&ua);
        const __half2* hb = reinterpret_cast<const __half2*>(&ub);
        #pragma unroll
        for (int k = 0; k < 4; k++) {
            float2 fa = __half22float2(ha[k]);
            float2 fb = __half22float2(hb[k]);
            float2 ov; ov.x = fa.x + fb.x; ov.y = fa.y + fb.y;
            *reinterpret_cast<float2*>(o + 2 * k) = ov;
        }
        float2 fa = __half22float2(*reinterpret_cast<const __half2*>(&ua2));
        float2 fb = __half22float2(*reinterpret_cast<const __half2*>(&ub2));
        float2 ov; ov.x = fa.x + fb.x; ov.y = fa.y + fb.y;
        *reinterpret_cast<float2*>(o + 8) = ov;
    } else {
        for (int k = 0; k < C; k++)
            o[k] = __half2float(a[k]) + __half2float(b[k]);
    }
}

// ---------------- host launch ----------------
extern "C" void kernel_launch(void* const* d_in, const int* in_sizes, int n_in,
                              void* d_out, int out_size)
{
    const float* x_user  = (const float*)d_in[0];
    const float* x_movie = (const float*)d_in[1];
    const void*  eidx    = d_in[2];
    const float* Wu = (const float*)d_in[3];
    const float* bu = (const float*)d_in[4];
    const float* Wm = (const float*)d_in[5];
    const float* bm = (const float*)d_in[6];
    const float* W1 = (const float*)d_in[7];
    const float* b1 = (const float*)d_in[8];
    const float* W2 = (const float*)d_in[9];
    const float* b2 = (const float*)d_in[10];
    const float* We = (const float*)d_in[11];
    const float* be = (const float*)d_in[12];
    float* out = (float*)d_out;

    const int H  = in_sizes[4];
    const int Fu = in_sizes[3] / H;
    const int Fm = in_sizes[5] / H;
    const int Nu = in_sizes[0] / Fu;
    const int Nm = in_sizes[1] / Fm;
    int E        = in_sizes[2] / 2;
    const int C  = in_sizes[12];
    const int Ntot = Nu + Nm;
    if (E > MAX_E) E = MAX_E;

    __half* xhp; cudaGetSymbolAddress((void**)&xhp, g_xh);
    __half* hp;  cudaGetSymbolAddress((void**)&hp,  g_hsh);

    cudaFuncSetAttribute(mp_wmma_linear_h_kernel,
                         cudaFuncAttributeMaxDynamicSharedMemorySize, SMEM_LIN);
    cudaFuncSetAttribute(mp_wmma_linear_kernel,
                         cudaFuncAttributeMaxDynamicSharedMemorySize, SMEM_LIN);
    cudaFuncSetAttribute(mp_fused1_kernel<32, 64>,
                         cudaFuncAttributeMaxDynamicSharedMemorySize, SMEM_F64);
    cudaFuncSetAttribute(mp_transform_kernel<32, 64>,
                         cudaFuncAttributeMaxDynamicSharedMemorySize, SMEM_F64);
    cudaFuncSetAttribute(mp_transform_kernel<128, 128>,
                         cudaFuncAttributeMaxDynamicSharedMemorySize, SMEM_F128);

    const int nb = (Ntot + SCAN_B - 1) / SCAN_B;
    const int EB = (E + 255) / 256;
    const bool fusedOK = (Fu == 32 && Fm == 64 && H == H_DIM);

    // launch 1: edge convert + degree count (+ weight-prep blocks)
    int wb = fusedOK
        ? (128 * Fu + 128 * Fm + 256 + 128 * 128 + 255) / 256 : 0;
    mp_convert_kernel<<<EB + wb, 256>>>(eidx, E, EB,
                                        Wu, bu, Wm, bm, W1, b1, W2, Fu, Fm);
    mp_scan1_kernel<<<nb, SCAN_B>>>(Ntot);                 // launch 2
    mp_scan3_kernel<<<(Ntot + 255) / 256, 256>>>(Ntot);    // launch 3

    int gU = (Nu + 127) / 128;
    int gM = (Nm + 127) / 128;
    int gW = (Ntot + 127) / 128;
    int gA = (int)(((long long)Ntot * 32 + 255) / 256);
    int gF = (E + TG - 1) / TG;

    // launch 4 (profiled): fused layer-1 GEMM + absorbed csr fill
    if (fusedOK) {
        mp_fused1_kernel<32, 64><<<gU + gM + gF, TG, SMEM_F64>>>(
            x_user, Nu, x_movie, Nm, hp, gU, gM, E);
    } else {
        if (Fu == 128 && Fm == 128)
            mp_transform_kernel<128, 128><<<gU + gM, TG, SMEM_F128>>>(
                x_user, Nu, Wu, bu, x_movie, Nm, Wm, bm, xhp, gU);
        else
            mp_transform_kernel<32, 64><<<gU + gM, TG, SMEM_F64>>>(
                x_user, Nu, Wu, bu, x_movie, Nm, Wm, bm, xhp, gU);
        mp_wmma_linear_kernel<<<gW, TG, SMEM_LIN>>>(xhp, Ntot, W1, b1, hp);
        mp_fill_kernel<<<EB, 256>>>(E);
    }

    // layer 1 aggregate -> xh
    mp_aggregate_kernel<false><<<gA, 256>>>(Ntot, Nu, nullptr, nullptr, 0);

    // GNN layer 2
    if (fusedOK)
        mp_wmma_linear_h_kernel<<<gW, TG, SMEM_LIN>>>(xhp, Ntot, b2, hp);
    else
        mp_wmma_linear_kernel<<<gW, TG, SMEM_LIN>>>(xhp, Ntot, W2, b2, hp);

    // layer 2 aggregate fused with edge-head projection (C <= MAX_C)
    if (C <= MAX_C) {
        mp_aggregate_kernel<true><<<gA, 256>>>(Ntot, Nu, We, be, C);
    } else {
        mp_aggregate_kernel<false><<<gA, 256>>>(Ntot, Nu, nullptr, nullptr, 0);
        mp_proj_kernel<<<(Ntot + 255) / 256, 256>>>(We, be, Nu, Nm, C);
    }

    // Per-edge output: gather + add
    mp_edge_out_kernel<<<(E + 255) / 256, 256>>>(out, E, C);
}

// round 16
// speedup vs baseline: 1.3792x; 1.3792x over previous
#include <cuda_runtime.h>
#include <cuda_fp16.h>
#include <mma.h>
#include <cstdint>
#include <cstddef>

using namespace nvcuda;

#define H_DIM 128
#define MAX_E 1048576
#define MAX_NODES 100480
#define MAX_SIDE 51200
#define PSH 16                         // fp16 p-table stride (halfs)
#define MAX_C 12
#define SCAN_B 256
#define MAX_SCAN_BLK 512
#define WLD 136                        // padded ld for 128-wide fp16 weight tile
#define LDKU 40                        // padded ld, K=32
#define LDKM 72                        // padded ld, K=64
#define ST_LD 20                       // per-warp stage ld (floats)
#define ST_WARP (16 * ST_LD)           // 320 floats = 1280 B per warp
#define TG 512                         // threads per GEMM block (16 warps)
#define SMEM_F64  (2 * 128 * LDKM * 2)         // fused1 <32,64>: 36864
#define SMEM_F128 (2 * 128 * (128 + 8) * 2)    // fallback <128,128>: 69632
#define SMEM_LIN  (128 * WLD * 2)              // layer GEMM: 34816

// ---------------- device scratch (no allocations allowed) ----------------
__device__ __align__(16) __half g_xh [(size_t)MAX_NODES * H_DIM];  // fp16 x
__device__ __align__(16) __half g_hsh[(size_t)MAX_NODES * H_DIM];  // fp16 hs
__device__ int   g_deg   [MAX_NODES];        // all-zero at entry; restored in scan3
__device__ int   g_off   [MAX_NODES + 1];
__device__ int   g_cursor[MAX_NODES];
__device__ float g_dinv  [MAX_NODES];
__device__ int   g_row[MAX_E];
__device__ int   g_col[MAX_E];
__device__ int   g_csr[MAX_E];            // source node per bucketed edge
__device__ int   g_bsum [MAX_SCAN_BLK];
__device__ __align__(16) __half g_puh[(size_t)MAX_SIDE * PSH];
__device__ __align__(16) __half g_pmh[(size_t)MAX_SIDE * PSH];
// combined layer-1 weights (fp16, padded layouts) + biases (fp32)
__device__ __align__(16) __half g_W1uh[128 * LDKU];
__device__ __align__(16) __half g_W1mh[128 * LDKM];
__device__ __align__(16) __half g_W2h [128 * WLD];
__device__ float g_b1u[128];
__device__ float g_b1m[128];

__device__ __forceinline__ uint2 f4_to_h4(float4 v)
{
    __half2 h0 = __floats2half2_rn(v.x, v.y);
    __half2 h1 = __floats2half2_rn(v.z, v.w);
    uint2 u;
    u.x = *reinterpret_cast<uint32_t*>(&h0);
    u.y = *reinterpret_cast<uint32_t*>(&h1);
    return u;
}

// ---------------- convert edges + degree count; spare blocks prep weights ------
__global__ void mp_convert_kernel(const void* ei, int E, int EB,
                                  const float* __restrict__ Wu,
                                  const float* __restrict__ bu,
                                  const float* __restrict__ Wm,
                                  const float* __restrict__ bm,
                                  const float* __restrict__ W1,
                                  const float* __restrict__ b1,
                                  const float* __restrict__ W2,
                                  int Fu, int Fm)
{
    if ((int)blockIdx.x < EB) {
        const long long* p64 = (const long long*)ei;
        long long probe = p64[threadIdx.x & 31];
        unsigned ok = __ballot_sync(0xffffffffu,
                                    probe >= 0 && probe < (1LL << 32));
        bool is64 = (ok == 0xffffffffu);

        int e = blockIdx.x * blockDim.x + threadIdx.x;
        if (e >= E) return;
        int r, c;
        if (is64) {
            r = (int)p64[e];
            c = (int)p64[(size_t)E + e];
        } else {
            const int* p = (const int*)ei;
            r = p[e];
            c = p[E + e];
        }
        g_row[e] = r;
        g_col[e] = c;
        atomicAdd(&g_deg[c], 1);
    } else {
        int idx = ((int)blockIdx.x - EB) * blockDim.x + threadIdx.x;
        int totU = 128 * Fu, totM = 128 * Fm;
        if (idx < totU) {
            int o = idx / Fu, f = idx - o * Fu;
            float s = 0.f;
            for (int j = 0; j < 128; j++) s += W1[o * 128 + j] * Wu[j * Fu + f];
            g_W1uh[o * LDKU + f] = __float2half_rn(s);
        } else if (idx < totU + totM) {
            int k = idx - totU;
            int o = k / Fm, f = k - o * Fm;
            float s = 0.f;
            for (int j = 0; j < 128; j++) s += W1[o * 128 + j] * Wm[j * Fm + f];
            g_W1mh[o * LDKM + f] = __float2half_rn(s);
        } else if (idx < totU + totM + 256) {
            int k = idx - totU - totM;
            int o = k & 127;
            bool isM = k >= 128;
            const float* bb = isM ? bm : bu;
            float s = b1[o];
            for (int j = 0; j < 128; j++) s += W1[o * 128 + j] * bb[j];
            if (isM) g_b1m[o] = s; else g_b1u[o] = s;
        } else if (idx < totU + totM + 256 + 128 * 128) {
            int k = idx - totU - totM - 256;
            int o = k >> 7, f = k & 127;
            g_W2h[o * WLD + f] = __float2half_rn(W2[o * 128 + f]);
        }
    }
}

// ---------------- scan phase 1: per-block exclusive scan + block sums ----------
__global__ void mp_scan1_kernel(int N)
{
    __shared__ int sh[SCAN_B];
    int t = threadIdx.x;
    int i = blockIdx.x * SCAN_B + t;
    int v = (i < N) ? g_deg[i] : 0;
    sh[t] = v;
    __syncthreads();
    #pragma unroll
    for (int ofs = 1; ofs < SCAN_B; ofs <<= 1) {
        int u = (t >= ofs) ? sh[t - ofs] : 0;
        __syncthreads();
        sh[t] += u;
        __syncthreads();
    }
    if (i < N) g_off[i] = sh[t] - v;
    if (t == SCAN_B - 1) g_bsum[blockIdx.x] = sh[t];
}

// ---------------- scan phase 2: block prefix + cursor/dinv init + deg restore --
__global__ void mp_scan3_kernel(int N)
{
    __shared__ int s_prefix;
    int t = threadIdx.x;
    if (t < 32) {
        int b = blockIdx.x;
        int sum = 0;
        for (int k = t; k < b; k += 32) sum += g_bsum[k];
        #pragma unroll
        for (int ofs = 16; ofs > 0; ofs >>= 1)
            sum += __shfl_down_sync(0xffffffffu, sum, ofs);
        if (t == 0) s_prefix = sum;
    }
    __syncthreads();
    int i = blockIdx.x * blockDim.x + t;
    if (i >= N) return;
    int d   = g_deg[i];
    int off = g_off[i] + s_prefix;
    g_off[i]    = off;
    g_cursor[i] = off;
    g_dinv[i]   = rsqrtf((float)(d + 1));
    g_deg[i]    = 0;                        // restore invariant
    if (i == N - 1) g_off[N] = off + d;
}

// ---------------- bucket fill: csr[pos] = row (standalone, fallback path) ------
__global__ void mp_fill_kernel(int E)
{
    int e = blockIdx.x * blockDim.x + threadIdx.x;
    if (e >= E) return;
    int pos = atomicAdd(&g_cursor[g_col[e]], 1);
    g_csr[pos] = g_row[e];
}

// ---------------- per-warp fragment epilogue: bias + optional scale -> fp16 ----
template<bool SCALE>
__device__ __forceinline__ void mp_epilogue_frag(
    float* st, wmma::fragment<wmma::accumulator, 16, 16, 16, float>& acc,
    int col0, int wrow0, int N, const float* __restrict__ B,
    const float* __restrict__ dinv_base, __half* __restrict__ Y, int lane)
{
    wmma::store_matrix_sync(st, acc, ST_LD, wmma::mem_row_major);
    __syncwarp();
    int r = lane >> 1;
    int h = lane & 1;
    int node = wrow0 + r;
    int c8 = col0 + h * 8;
    if (node < N) {
        float s = SCALE ? dinv_base[node] : 1.f;
        const float* sp = st + r * ST_LD + h * 8;
        float4 v0 = *reinterpret_cast<const float4*>(sp);
        float4 v1 = *reinterpret_cast<const float4*>(sp + 4);
        __half2 hh[4];
        hh[0] = __floats2half2_rn((v0.x + B[c8 + 0]) * s, (v0.y + B[c8 + 1]) * s);
        hh[1] = __floats2half2_rn((v0.z + B[c8 + 2]) * s, (v0.w + B[c8 + 3]) * s);
        hh[2] = __floats2half2_rn((v1.x + B[c8 + 4]) * s, (v1.y + B[c8 + 5]) * s);
        hh[3] = __floats2half2_rn((v1.z + B[c8 + 6]) * s, (v1.w + B[c8 + 7]) * s);
        *reinterpret_cast<uint4*>(Y + (size_t)node * H_DIM + c8) =
            *reinterpret_cast<const uint4*>(hh);
    }
    __syncwarp();
}

// ---------------- wmma node linear, pre-converted fp16 weights (padded LDK) ----
template<int K>
__device__ __forceinline__ void mp_wmma_xf16_body(
    const float* __restrict__ X, int N,
    const __half* __restrict__ Wg,       // [128][K+8] fp16, pre-padded
    const float* __restrict__ B,
    const float* __restrict__ dinv_base,
    __half* __restrict__ Y, int bid)
{
    constexpr int LDK = K + 8;
    extern __shared__ __align__(16) char smem_raw[];
    __half* Xh    = reinterpret_cast<__half*>(smem_raw);   // 128 x LDK
    __half* Wh    = Xh + 128 * LDK;                        // 128 x LDK
    float*  stage = reinterpret_cast<float*>(smem_raw);    // overlays after loop

    const int tid  = threadIdx.x;
    const int w    = tid >> 5;
    const int lane = tid & 31;
    const int wr   = w >> 1;
    const int wc   = w & 1;
    const int tile0 = bid * 128;
    const int wrow0 = tile0 + wr * 16;

    constexpr int KV = K / 4;
    for (int i = tid; i < 128 * KV; i += TG) {
        int n = i / KV, q = i - n * KV;
        int node = tile0 + n;
        if (node >= N) node = N - 1;                       // stores guarded
        float4 v = *reinterpret_cast<const float4*>(X + (size_t)node * K + q * 4);
        *reinterpret_cast<uint2*>(Xh + n * LDK + q * 4) = f4_to_h4(v);
    }
    for (int i = tid; i < 128 * LDK / 8; i += TG)
        reinterpret_cast<uint4*>(Wh)[i] =
            reinterpret_cast<const uint4*>(Wg)[i];
    __syncthreads();

    wmma::fragment<wmma::accumulator, 16, 16, 16, float> acc[4];
    #pragma unroll
    for (int n = 0; n < 4; n++) wmma::fill_fragment(acc[n], 0.f);

    #pragma unroll
    for (int k0 = 0; k0 < K / 16; k0++) {
        wmma::fragment<wmma::matrix_a, 16, 16, 16, __half, wmma::row_major> a;
        wmma::load_matrix_sync(a, Xh + wr * 16 * LDK + k0 * 16, LDK);
        #pragma unroll
        for (int n = 0; n < 4; n++) {
            wmma::fragment<wmma::matrix_b, 16, 16, 16, __half, wmma::col_major> b;
            wmma::load_matrix_sync(b, Wh + (wc * 64 + n * 16) * LDK + k0 * 16, LDK);
            wmma::mma_sync(acc[n], a, b, acc[n]);
        }
    }
    __syncthreads();   // tiles dead; per-warp stage overlays them

    float* st = stage + w * ST_WARP;
    #pragma unroll
    for (int n = 0; n < 4; n++)
        mp_epilogue_frag<true>(st, acc[n], wc * 64 + n * 16, wrow0, N,
                               B, dinv_base, Y, lane);
}

// Fused layer-1 (+ absorbed bucket fill in tail blocks).
template<int KU, int KM>
__global__ void __launch_bounds__(TG)
mp_fused1_kernel(const float* __restrict__ Xu, int Nu,
                 const float* __restrict__ Xm, int Nm,
                 __half* __restrict__ Y, int gU, int gM, int E)
{
    int b = (int)blockIdx.x;
    if (b < gU) {
        mp_wmma_xf16_body<KU>(Xu, Nu, g_W1uh, g_b1u, g_dinv, Y, b);
    } else if (b < gU + gM) {
        mp_wmma_xf16_body<KM>(Xm, Nm, g_W1mh, g_b1m, g_dinv + Nu,
                              Y + (size_t)Nu * H_DIM, b - gU);
    } else {
        int e = (b - gU - gM) * TG + threadIdx.x;
        if (e < E) {
            int pos = atomicAdd(&g_cursor[g_col[e]], 1);
            g_csr[pos] = g_row[e];
        }
    }
}

// ---------------- fallback fp32-weight body (odd K shapes) ---------------------
template<int K, bool SCALE>
__device__ __forceinline__ void mp_wmma_xf_body(
    const float* __restrict__ X, int N,
    const float* __restrict__ W,
    const float* __restrict__ B,
    const float* __restrict__ dinv_base,
    __half* __restrict__ Y, int bid)
{
    constexpr int LDK = K + 8;
    extern __shared__ __align__(16) char smem_raw[];
    __half* Xh    = reinterpret_cast<__half*>(smem_raw);
    __half* Wh    = Xh + 128 * LDK;
    float*  stage = reinterpret_cast<float*>(smem_raw);

    const int tid  = threadIdx.x;
    const int w    = tid >> 5;
    const int lane = tid & 31;
    const int wr   = w >> 1;
    const int wc   = w & 1;
    const int tile0 = bid * 128;
    const int wrow0 = tile0 + wr * 16;

    constexpr int KV = K / 4;
    for (int i = tid; i < 128 * KV; i += TG) {
        int n = i / KV, q = i - n * KV;
        int node = tile0 + n;
        if (node >= N) node = N - 1;
        float4 v = *reinterpret_cast<const float4*>(X + (size_t)node * K + q * 4);
        *reinterpret_cast<uint2*>(Xh + n * LDK + q * 4) = f4_to_h4(v);
    }
    for (int i = tid; i < 128 * KV; i += TG) {
        int n = i / KV, q = i - n * KV;
        float4 v = *reinterpret_cast<const float4*>(W + (size_t)n * K + q * 4);
        *reinterpret_cast<uint2*>(Wh + n * LDK + q * 4) = f4_to_h4(v);
    }
    __syncthreads();

    wmma::fragment<wmma::accumulator, 16, 16, 16, float> acc[4];
    #pragma unroll
    for (int n = 0; n < 4; n++) wmma::fill_fragment(acc[n], 0.f);

    #pragma unroll
    for (int k0 = 0; k0 < K / 16; k0++) {
        wmma::fragment<wmma::matrix_a, 16, 16, 16, __half, wmma::row_major> a;
        wmma::load_matrix_sync(a, Xh + wr * 16 * LDK + k0 * 16, LDK);
        #pragma unroll
        for (int n = 0; n < 4; n++) {
            wmma::fragment<wmma::matrix_b, 16, 16, 16, __half, wmma::col_major> b;
            wmma::load_matrix_sync(b, Wh + (wc * 64 + n * 16) * LDK + k0 * 16, LDK);
            wmma::mma_sync(acc[n], a, b, acc[n]);
        }
    }
    __syncthreads();

    float* st = stage + w * ST_WARP;
    #pragma unroll
    for (int n = 0; n < 4; n++)
        mp_epilogue_frag<SCALE>(st, acc[n], wc * 64 + n * 16, wrow0, N,
                                B, dinv_base, Y, lane);
}

template<int KU, int KM>
__global__ void __launch_bounds__(TG)
mp_transform_kernel(const float* __restrict__ Xu, int Nu,
                    const float* __restrict__ Wu,
                    const float* __restrict__ Bu,
                    const float* __restrict__ Xm, int Nm,
                    const float* __restrict__ Wm,
                    const float* __restrict__ Bm,
                    __half* __restrict__ Y, int gU)
{
    if ((int)blockIdx.x < gU)
        mp_wmma_xf_body<KU, false>(Xu, Nu, Wu, Bu, nullptr, Y, blockIdx.x);
    else
        mp_wmma_xf_body<KM, false>(Xm, Nm, Wm, Bm, nullptr,
                                   Y + (size_t)Nu * H_DIM, blockIdx.x - gU);
}

// ---------------- layer GEMM, pre-converted fp16 W2 (padded WLD) ---------------
__global__ void __launch_bounds__(TG)
mp_wmma_linear_h_kernel(const __half* __restrict__ A, int N,
                        const float* __restrict__ B,
                        __half* __restrict__ Y)
{
    extern __shared__ __align__(16) char smem_raw[];
    __half* Wh    = reinterpret_cast<__half*>(smem_raw);   // 128 x WLD
    float*  stage = reinterpret_cast<float*>(smem_raw);    // overlays Wh

    const int tid  = threadIdx.x;
    const int w    = tid >> 5;
    const int lane = tid & 31;
    const int wr   = w >> 1;
    const int wc   = w & 1;
    const int wrow0 = blockIdx.x * 128 + wr * 16;

    for (int i = tid; i < 128 * WLD / 8; i += TG)
        reinterpret_cast<uint4*>(Wh)[i] =
            reinterpret_cast<const uint4*>(g_W2h)[i];
    __syncthreads();

    wmma::fragment<wmma::accumulator, 16, 16, 16, float> acc[4];
    #pragma unroll
    for (int n = 0; n < 4; n++) wmma::fill_fragment(acc[n], 0.f);

    int arow = wrow0;
    if (arow + 16 > N) arow = (N > 16) ? N - 16 : 0;

    #pragma unroll
    for (int k0 = 0; k0 < 8; k0++) {
        wmma::fragment<wmma::matrix_a, 16, 16, 16, __half, wmma::row_major> a;
        wmma::load_matrix_sync(a, A + (size_t)arow * H_DIM + k0 * 16, H_DIM);
        #pragma unroll
        for (int n = 0; n < 4; n++) {
            wmma::fragment<wmma::matrix_b, 16, 16, 16, __half, wmma::col_major> b;
            wmma::load_matrix_sync(b, Wh + (wc * 64 + n * 16) * WLD + k0 * 16, WLD);
            wmma::mma_sync(acc[n], a, b, acc[n]);
        }
    }
    __syncthreads();

    float* st = stage + w * ST_WARP;
    #pragma unroll
    for (int n = 0; n < 4; n++)
        mp_epilogue_frag<true>(st, acc[n], wc * 64 + n * 16, arow, N,
                               B, g_dinv, Y, lane);
}

// Fallback layer GEMM with fp32 W conversion in-kernel.
__global__ void __launch_bounds__(TG)
mp_wmma_linear_kernel(const __half* __restrict__ A, int N,
                      const float* __restrict__ W,
                      const float* __restrict__ B,
                      __half* __restrict__ Y)
{
    extern __shared__ __align__(16) char smem_raw[];
    __half* Wh    = reinterpret_cast<__half*>(smem_raw);
    float*  stage = reinterpret_cast<float*>(smem_raw);

    const int tid  = threadIdx.x;
    const int w    = tid >> 5;
    const int lane = tid & 31;
    const int wr   = w >> 1;
    const int wc   = w & 1;
    const int wrow0 = blockIdx.x * 128 + wr * 16;

    for (int i = tid; i < 128 * 64; i += TG) {
        int o = i >> 6, q = i & 63;
        float2 v = reinterpret_cast<const float2*>(W + (size_t)o * 128)[q];
        reinterpret_cast<__half2*>(Wh + o * WLD)[q] = __floats2half2_rn(v.x, v.y);
    }
    __syncthreads();

    wmma::fragment<wmma::accumulator, 16, 16, 16, float> acc[4];
    #pragma unroll
    for (int n = 0; n < 4; n++) wmma::fill_fragment(acc[n], 0.f);

    int arow = wrow0;
    if (arow + 16 > N) arow = (N > 16) ? N - 16 : 0;

    #pragma unroll
    for (int k0 = 0; k0 < 8; k0++) {
        wmma::fragment<wmma::matrix_a, 16, 16, 16, __half, wmma::row_major> a;
        wmma::load_matrix_sync(a, A + (size_t)arow * H_DIM + k0 * 16, H_DIM);
        #pragma unroll
        for (int n = 0; n < 4; n++) {
            wmma::fragment<wmma::matrix_b, 16, 16, 16, __half, wmma::col_major> b;
            wmma::load_matrix_sync(b, Wh + (wc * 64 + n * 16) * WLD + k0 * 16, WLD);
            wmma::mma_sync(acc[n], a, b, acc[n]);
        }
    }
    __syncthreads();

    float* st = stage + w * ST_WARP;
    #pragma unroll
    for (int n = 0; n < 4; n++)
        mp_epilogue_frag<true>(st, acc[n], wc * 64 + n * 16, arow, N,
                               B, g_dinv, Y, lane);
}

// ---------------- aggregate: xh[n] = fp16(relu(dinv[n]*(hs[n] + sum hs[src]))) --
__device__ __forceinline__ void mp_acc_add8(float* a, uint4 v)
{
    const __half2* hv = reinterpret_cast<const __half2*>(&v);
    #pragma unroll
    for (int k = 0; k < 4; k++) {
        float2 f = __half22float2(hv[k]);
        a[2 * k]     += f.x;
        a[2 * k + 1] += f.y;
    }
}

__global__ void mp_aggregate_kernel(int N)
{
    int id = blockIdx.x * blockDim.x + threadIdx.x;
    int n = id >> 5;
    if (n >= N) return;
    int lane = id & 31;
    int half = lane >> 4;
    int hl   = lane & 15;

    const uint4* hsp = reinterpret_cast<const uint4*>(g_hsh);   // row = 16 uint4

    float a[8];
    #pragma unroll
    for (int c = 0; c < 8; c++) a[c] = 0.f;

    if (half == 0)                                              // self-loop
        mp_acc_add8(a, __ldg(hsp + (size_t)n * 16 + hl));

    int beg = g_off[n];
    int end = g_off[n + 1];
    for (int base = beg; base < end; base += 32) {
        int m = end - base;
        if (m > 32) m = 32;
        int idx = (lane < m) ? g_csr[base + lane] : 0;
        int j = 0;
        for (; j + 2 <= m; j += 2) {
            int r = __shfl_sync(0xffffffffu, idx, j + half);
            mp_acc_add8(a, __ldg(hsp + (size_t)r * 16 + hl));
        }
        if (j < m) {                                            // odd tail
            int r = __shfl_sync(0xffffffffu, idx, j);
            if (half == 0)
                mp_acc_add8(a, __ldg(hsp + (size_t)r * 16 + hl));
        }
    }

    #pragma unroll
    for (int c = 0; c < 8; c++)
        a[c] += __shfl_xor_sync(0xffffffffu, a[c], 16);

    if (half == 0) {
        float s = g_dinv[n];
        __half2 h[4];
        #pragma unroll
        for (int j = 0; j < 4; j++)
            h[j] = __floats2half2_rn(fmaxf(a[2 * j] * s, 0.f),
                                     fmaxf(a[2 * j + 1] * s, 0.f));
        reinterpret_cast<uint4*>(g_xh)[(size_t)n * 16 + hl] =
            *reinterpret_cast<const uint4*>(h);
    }
}

// ---------------- node projection to C dims (fp16 x -> fp16 p tables) ----------
__global__ void mp_proj_kernel(const float* __restrict__ We,
                               const float* __restrict__ be,
                               int Nu, int Nm, int C)
{
    __shared__ float WeS[MAX_C][2 * H_DIM];
    __shared__ float beS[MAX_C];
    int tid = threadIdx.x;
    for (int i = tid; i < C * 2 * H_DIM; i += blockDim.x)
        WeS[i / (2 * H_DIM)][i % (2 * H_DIM)] = We[i];
    if (tid < C) beS[tid] = be[tid];
    __syncthreads();

    int n = blockIdx.x * blockDim.x + tid;
    if (n >= Nu + Nm) return;
    bool isU = n < Nu;
    const uint2* src = reinterpret_cast<const uint2*>(g_xh + (size_t)n * H_DIM);
    int wo = isU ? 0 : H_DIM;

    float acc[MAX_C];
    #pragma unroll
    for (int c = 0; c < MAX_C; c++) acc[c] = (c < C && isU) ? beS[c] : 0.f;

    #pragma unroll 4
    for (int q = 0; q < H_DIM / 4; q++) {
        uint2 u = src[q];
        __half2 ah = *reinterpret_cast<__half2*>(&u.x);
        __half2 bh = *reinterpret_cast<__half2*>(&u.y);
        float2 fa = __half22float2(ah);
        float2 fb = __half22float2(bh);
        int k = q * 4 + wo;
        #pragma unroll
        for (int c = 0; c < MAX_C; c++) {
            if (c < C) {
                acc[c] += fa.x * WeS[c][k + 0] + fa.y * WeS[c][k + 1]
                        + fb.x * WeS[c][k + 2] + fb.y * WeS[c][k + 3];
            }
        }
    }

    __half* dst = isU ? (g_puh + (size_t)n * PSH)
                      : (g_pmh + (size_t)(n - Nu) * PSH);
    if ((C & 1) == 0) {
        for (int c = 0; c < C; c += 2)
            *reinterpret_cast<__half2*>(dst + c) =
                __floats2half2_rn(acc[c], acc[c + 1]);
    } else {
        for (int c = 0; c < C; c++) dst[c] = __float2half_rn(acc[c]);
    }
}

// ---------------- out[e] = pu[row[e]] + pm[col[e]]  (fp16 tables, fp32 out) -----
__global__ void mp_edge_out_kernel(float* __restrict__ out, int E, int C)
{
    int e = blockIdx.x * blockDim.x + threadIdx.x;
    if (e >= E) return;
    int r = g_row[e];
    int c = g_col[e];
    const __half* a = g_puh + (size_t)r * PSH;
    const __half* b = g_pmh + (size_t)c * PSH;
    float* o = out + (size_t)e * C;
    if (C == 10) {
        uint4 ua = *reinterpret_cast<const uint4*>(a);
        uint4 ub = *reinterpret_cast<const uint4*>(b);
        uint32_t ua2 = *reinterpret_cast<const uint32_t*>(a + 8);
        uint32_t ub2 = *reinterpret_cast<const uint32_t*>(b + 8);
        const __half2* ha = reinterpret_cast<const __half2*>(&ua);
        const __half2* hb = reinterpret_cast<const __half2*>(&ub);
        #pragma unroll
        for (int k = 0; k < 4; k++) {
            float2 fa = __half22float2(ha[k]);
            float2 fb = __half22float2(hb[k]);
            float2 ov; ov.x = fa.x + fb.x; ov.y = fa.y + fb.y;
            *reinterpret_cast<float2*>(o + 2 * k) = ov;
        }
        float2 fa = __half22float2(*reinterpret_cast<const __half2*>(&ua2));
        float2 fb = __half22float2(*reinterpret_cast<const __half2*>(&ub2));
        float2 ov; ov.x = fa.x + fb.x; ov.y = fa.y + fb.y;
        *reinterpret_cast<float2*>(o + 8) = ov;
    } else {
        for (int k = 0; k < C; k++)
            o[k] = __half2float(a[k]) + __half2float(b[k]);
    }
}

// ---------------- host launch ----------------
extern "C" void kernel_launch(void* const* d_in, const int* in_sizes, int n_in,
                              void* d_out, int out_size)
{
    const float* x_user  = (const float*)d_in[0];
    const float* x_movie = (const float*)d_in[1];
    const void*  eidx    = d_in[2];
    const float* Wu = (const float*)d_in[3];
    const float* bu = (const float*)d_in[4];
    const float* Wm = (const float*)d_in[5];
    const float* bm = (const float*)d_in[6];
    const float* W1 = (const float*)d_in[7];
    const float* b1 = (const float*)d_in[8];
    const float* W2 = (const float*)d_in[9];
    const float* b2 = (const float*)d_in[10];
    const float* We = (const float*)d_in[11];
    const float* be = (const float*)d_in[12];
    float* out = (float*)d_out;

    const int H  = in_sizes[4];
    const int Fu = in_sizes[3] / H;
    const int Fm = in_sizes[5] / H;
    const int Nu = in_sizes[0] / Fu;
    const int Nm = in_sizes[1] / Fm;
    int E        = in_sizes[2] / 2;
    const int C  = in_sizes[12];
    const int Ntot = Nu + Nm;
    if (E > MAX_E) E = MAX_E;

    __half* xhp; cudaGetSymbolAddress((void**)&xhp, g_xh);
    __half* hp;  cudaGetSymbolAddress((void**)&hp,  g_hsh);

    cudaFuncSetAttribute(mp_wmma_linear_h_kernel,
                         cudaFuncAttributeMaxDynamicSharedMemorySize, SMEM_LIN);
    cudaFuncSetAttribute(mp_wmma_linear_kernel,
                         cudaFuncAttributeMaxDynamicSharedMemorySize, SMEM_LIN);
    cudaFuncSetAttribute(mp_fused1_kernel<32, 64>,
                         cudaFuncAttributeMaxDynamicSharedMemorySize, SMEM_F64);
    cudaFuncSetAttribute(mp_transform_kernel<32, 64>,
                         cudaFuncAttributeMaxDynamicSharedMemorySize, SMEM_F64);
    cudaFuncSetAttribute(mp_transform_kernel<128, 128>,
                         cudaFuncAttributeMaxDynamicSharedMemorySize, SMEM_F128);

    const int nb = (Ntot + SCAN_B - 1) / SCAN_B;
    const int EB = (E + 255) / 256;
    const bool fusedOK = (Fu == 32 && Fm == 64 && H == H_DIM);

    // launch 1: edge convert + degree count (+ weight-prep blocks)
    int wb = fusedOK
        ? (128 * Fu + 128 * Fm + 256 + 128 * 128 + 255) / 256 : 0;
    mp_convert_kernel<<<EB + wb, 256>>>(eidx, E, EB,
                                        Wu, bu, Wm, bm, W1, b1, W2, Fu, Fm);
    mp_scan1_kernel<<<nb, SCAN_B>>>(Ntot);                 // launch 2
    mp_scan3_kernel<<<(Ntot + 255) / 256, 256>>>(Ntot);    // launch 3

    int gU = (Nu + 127) / 128;
    int gM = (Nm + 127) / 128;
    int gW = (Ntot + 127) / 128;
    int gA = (int)(((long long)Ntot * 32 + 255) / 256);
    int gF = (E + TG - 1) / TG;

    // launch 4 (profiled): fused layer-1 GEMM + absorbed csr fill
    if (fusedOK) {
        mp_fused1_kernel<32, 64><<<gU + gM + gF, TG, SMEM_F64>>>(
            x_user, Nu, x_movie, Nm, hp, gU, gM, E);
    } else {
        if (Fu == 128 && Fm == 128)
            mp_transform_kernel<128, 128><<<gU + gM, TG, SMEM_F128>>>(
                x_user, Nu, Wu, bu, x_movie, Nm, Wm, bm, xhp, gU);
        else
            mp_transform_kernel<32, 64><<<gU + gM, TG, SMEM_F64>>>(
                x_user, Nu, Wu, bu, x_movie, Nm, Wm, bm, xhp, gU);
        mp_wmma_linear_kernel<<<gW, TG, SMEM_LIN>>>(xhp, Ntot, W1, b1, hp);
        mp_fill_kernel<<<EB, 256>>>(E);
    }

    // layer 1 aggregate -> xh
    mp_aggregate_kernel<<<gA, 256>>>(Ntot);

    // GNN layer 2
    if (fusedOK)
        mp_wmma_linear_h_kernel<<<gW, TG, SMEM_LIN>>>(xhp, Ntot, b2, hp);
    else
        mp_wmma_linear_kernel<<<gW, TG, SMEM_LIN>>>(xhp, Ntot, W2, b2, hp);
    mp_aggregate_kernel<<<gA, 256>>>(Ntot);

    // Edge head: project nodes to C dims, then gather+add per edge
    mp_proj_kernel<<<(Ntot + 255) / 256, 256>>>(We, be, Nu, Nm, C);
    mp_edge_out_kernel<<<(E + 255) / 256, 256>>>(out, E, C);
}